// round 11
// baseline (speedup 1.0000x reference)
#include <cuda_runtime.h>
#include <cuda_bf16.h>
#include <math.h>

typedef unsigned long long ull;
typedef unsigned int uint32;

#define V_VOCAB 50257
#define VP2     50432          // 197 tiles * 256
#define NVT2    197
#define HID     512
#define NB      32
#define TT      128
#define NSTEP   127
#define NROWS   4064
#define RPAD    4096           // 32 row tiles * 128
#define NBLK    128            // persistent GRU blocks

// emit tile: M=128 x N=256, K=512 in 16 stages of 32; 6-deep bulk ring
#define TM      128
#define TN      256
#define NSTG    16
#define ABLK    10240          // 128 rows * 80B
#define BBLK    20480          // 256 rows * 80B
#define STG1    (ABLK + BBLK)  // 30720
#define NRING   6
#define DYNB    (NRING * STG1) // 184320

// prepAll virtual index space
#define NCW     ((size_t)NVT2 * 16 * 256 * 40)   // 32,276,480 conv items
#define PREP_TOTAL (NCW + VP2 + 16384 + 786432)

// ---------------- static device scratch ----------------
__device__ __align__(16) float g_Wt_ih[512 * 1536];               // W_ih transposed [k][j]
__device__ __align__(16) float g_Git[(size_t)NSTEP * 1536 * NB];  // gi, [t][j][n]
__device__ __align__(16) float g_Hst[128 * HID * NB];             // hidden states [t][k][n]
__device__ __align__(16) float g_bpad[VP2];                       // emit_b padded with -1e30
// B image: [vt][kc 16][vrow 256][40 bf16] — byte-exact smem tile, 80B rows
__device__ __align__(16) __nv_bfloat16 g_Wimg[(size_t)NVT2 * 16 * 256 * 40];
// A image: [bt 32][kc 16][mrow 128][40 bf16]
__device__ __align__(16) __nv_bfloat16 g_Aimg[(size_t)32 * 16 * 128 * 40];
__device__ float g_Pm[(size_t)NVT2 * RPAD];
__device__ float g_Ps[(size_t)NVT2 * RPAD];
__device__ float g_Tlog[NROWS];
__device__ unsigned int g_cnt = 0;   // grid barrier arrivals (self-resetting)
__device__ unsigned int g_gen = 0;   // grid barrier generation (monotonic)

__device__ __forceinline__ float sigmoidf_(float x) { return 1.0f / (1.0f + expf(-x)); }

__device__ __forceinline__ void lse_combine(float& M, float& S, float m2, float s2) {
    if (m2 > M) { S = S * expf(M - m2) + s2; M = m2; }
    else        { S += s2 * expf(m2 - M); }
}

// fast exp for x <= 0 on the FMA pipe (deg-5, rint-centered; rel err ~4e-7)
__device__ __forceinline__ float fexp(float x) {
    x = fmaxf(x, -20.0f);
    float t = x * 1.4426950408889634f;
    float fi = rintf(t);
    float f = t - fi;
    float p = 0.0013333558f;
    p = fmaf(p, f, 0.0096181291f);
    p = fmaf(p, f, 0.0555041087f);
    p = fmaf(p, f, 0.2402265070f);
    p = fmaf(p, f, 0.6931471806f);
    p = fmaf(p, f, 1.0f);
    int e = (int)fi;
    float s = __int_as_float((e + 127) << 23);
    return p * s;
}

// ---------------- f32x2 helpers (giK) ----------------
__device__ __forceinline__ ull pack2(float lo, float hi) {
    ull r; asm("mov.b64 %0, {%1, %2};" : "=l"(r) : "f"(lo), "f"(hi)); return r;
}
__device__ __forceinline__ float2 unpack2(ull v) {
    float2 f; asm("mov.b64 {%0, %1}, %2;" : "=f"(f.x), "=f"(f.y) : "l"(v)); return f;
}
__device__ __forceinline__ void ffma2(ull& acc, ull a, ull b) {
    asm("fma.rn.f32x2 %0, %1, %2, %0;" : "+l"(acc) : "l"(a), "l"(b));
}

// ---------------- mma / bulk helpers ----------------
__device__ __forceinline__ uint32 smem_u32(const void* p) {
    return (uint32)__cvta_generic_to_shared(p);
}
#define LDSM4(R, addr) asm volatile( \
    "ldmatrix.sync.aligned.m8n8.x4.shared.b16 {%0,%1,%2,%3}, [%4];" \
    : "=r"((R)[0]), "=r"((R)[1]), "=r"((R)[2]), "=r"((R)[3]) : "r"(addr))
#define MMA_BF16(D, A, B0, B1) asm volatile( \
    "mma.sync.aligned.m16n8k16.row.col.f32.bf16.bf16.f32 " \
    "{%0,%1,%2,%3}, {%4,%5,%6,%7}, {%8,%9}, {%0,%1,%2,%3};" \
    : "+f"((D)[0]), "+f"((D)[1]), "+f"((D)[2]), "+f"((D)[3]) \
    : "r"((A)[0]), "r"((A)[1]), "r"((A)[2]), "r"((A)[3]), "r"(B0), "r"(B1))
#define MBAR_INIT(mb, cnt) asm volatile( \
    "mbarrier.init.shared.b64 [%0], %1;" :: "r"(mb), "r"((uint32)(cnt)) : "memory")
#define EXPECT_TX(mb, bytes) asm volatile( \
    "mbarrier.arrive.expect_tx.shared.b64 _, [%0], %1;" :: "r"(mb), "r"((uint32)(bytes)) : "memory")
#define BULK(dst, src, bytes, mb) asm volatile( \
    "cp.async.bulk.shared::cluster.global.mbarrier::complete_tx::bytes [%0], [%1], %2, [%3];" \
    :: "r"(dst), "l"(src), "r"((uint32)(bytes)), "r"(mb) : "memory")
#define MBAR_WAIT(mb, par) do { \
    uint32 _mb = (mb); uint32 _p = (par); uint32 _done; \
    asm volatile("{\n\t.reg .pred p;\n\t" \
        "mbarrier.try_wait.parity.acquire.cta.shared::cta.b64 p, [%1], %2;\n\t" \
        "selp.b32 %0, 1, 0, p;\n\t}" : "=r"(_done) : "r"(_mb), "r"(_p) : "memory"); \
    if (!_done) { \
        asm volatile("{\n\t.reg .pred P1;\n\t" \
            "WL_%=:\n\t" \
            "mbarrier.try_wait.parity.acquire.cta.shared::cta.b64 P1, [%0], %1, 0x989680;\n\t" \
            "@P1 bra.uni WD_%=;\n\t" \
            "bra.uni WL_%=;\n\t" \
            "WD_%=:\n\t}" :: "r"(_mb), "r"(_p) : "memory"); \
    } \
} while (0)

// ---------------- merged prep: convWimg + bpad + initH + transpose W_ih ----------------
__global__ __launch_bounds__(256) void prepAll(const float* __restrict__ emit_W,
                                               const float* __restrict__ emit_b,
                                               const float* __restrict__ h0,
                                               const float* __restrict__ W_ih) {
    size_t idx = (size_t)blockIdx.x * 256 + threadIdx.x;
    if (idx < NCW) {
        // B image build: [vt][kc][vr][40], pad -> 0
        int c  = (int)(idx % 40);
        int vr = (int)((idx / 40) % 256);
        int kc = (int)((idx / (40 * 256)) % 16);
        int vt = (int)(idx / (40 * 256 * 16));
        int v = vt * 256 + vr, k = kc * 32 + c;
        float x = (c < 32 && v < V_VOCAB) ? emit_W[(size_t)v * 512 + k] : 0.0f;
        g_Wimg[idx] = __float2bfloat16(x);
        return;
    }
    idx -= NCW;
    if (idx < VP2) {
        g_bpad[idx] = (idx < V_VOCAB) ? emit_b[idx] : -1e30f;
        return;
    }
    idx -= VP2;
    if (idx < 16384) {
        int n = (int)(idx >> 9), k = (int)(idx & 511);
        g_Hst[k * NB + n] = h0[idx];
        return;
    }
    idx -= 16384;
    if (idx < 786432) {
        // g_Wt_ih[k*1536 + j] = W_ih[j*512 + k]  (coalesced write)
        int k = (int)(idx / 1536), j = (int)(idx % 1536);
        g_Wt_ih[idx] = W_ih[(size_t)j * 512 + k];
    }
}

// ---------------- gi GEMM ----------------
__global__ __launch_bounds__(256) void giK(const int* __restrict__ words,
                                           const float* __restrict__ embW,
                                           const float* __restrict__ b_ih) {
    int jc = blockIdx.x, rg = blockIdx.y;
    int tid = threadIdx.x, tx = tid & 63, ty = tid >> 6;
    __shared__ float ash[16 * 514];
    int rbase = rg * 16;
    for (int idx = tid; idx < 8192; idx += 256) {
        int i = idx >> 9, k = idx & 511;
        int r = rbase + i;
        int w = words[(r & 31) * TT + (r >> 5)];
        ash[i * 514 + k] = embW[(size_t)w * 512 + k];
    }
    __syncthreads();

    int j0 = jc * 512 + tx * 8;
    ull acc[4][4];
#pragma unroll
    for (int a = 0; a < 4; ++a)
#pragma unroll
        for (int b = 0; b < 4; ++b) acc[a][b] = 0ull;

    const float* wp = g_Wt_ih + j0;
    int rb = ty * 4;
#pragma unroll 4
    for (int k = 0; k < 512; ++k) {
        float4 wa = *(const float4*)(wp);
        float4 wb = *(const float4*)(wp + 4);
        wp += 1536;
        ull b0 = pack2(wa.x, wa.y), b1 = pack2(wa.z, wa.w);
        ull b2 = pack2(wb.x, wb.y), b3 = pack2(wb.z, wb.w);
#pragma unroll
        for (int ri = 0; ri < 4; ++ri) {
            float h = ash[(rb + ri) * 514 + k];
            ull a2 = pack2(h, h);
            ffma2(acc[ri][0], a2, b0);
            ffma2(acc[ri][1], a2, b1);
            ffma2(acc[ri][2], a2, b2);
            ffma2(acc[ri][3], a2, b3);
        }
    }

    int t = rbase >> 5;
#pragma unroll
    for (int ri = 0; ri < 4; ++ri) {
        int r = rbase + rb + ri;
        int n = r & 31;
#pragma unroll
        for (int p = 0; p < 4; ++p) {
            float2 l = unpack2(acc[ri][p]);
            int j = j0 + 2 * p;
            g_Git[((size_t)t * 1536 + j) * NB + n]     = l.x + b_ih[j];
            g_Git[((size_t)t * 1536 + j + 1) * NB + n] = l.y + b_ih[j + 1];
        }
    }
}

// ---------------- persistent GRU: 127 steps, cheap grid barrier ----------------
__global__ __launch_bounds__(512) void gruPersist(const float* __restrict__ W_hh,
                                                  const float* __restrict__ b_hh) {
    __shared__ float part[3][4][4][32];
    int tid = threadIdx.x;
    int n = tid & 31, ks = (tid >> 5) & 3, jl = tid >> 7;
    int bx = blockIdx.x;
    int j = bx * 4 + jl;
    unsigned int mygen = g_gen;

    int kb = ks * 128;
    const float* wr = W_hh + (size_t)j * 512 + kb;
    const float* wz = wr + 512 * 512;
    const float* wn = wz + 512 * 512;

    for (int t = 0; t < NSTEP; ++t) {
        const float* hp = g_Hst + (size_t)t * (HID * NB);
        const float* hb = hp + kb * NB;

        float ar = 0.f, az = 0.f, an = 0.f;
#pragma unroll 8
        for (int k = 0; k < 128; k += 4) {
            float4 r4 = *(const float4*)(wr + k);
            float4 z4 = *(const float4*)(wz + k);
            float4 n4 = *(const float4*)(wn + k);
            float h0 = hb[(k + 0) * NB + n];
            float h1 = hb[(k + 1) * NB + n];
            float h2 = hb[(k + 2) * NB + n];
            float h3 = hb[(k + 3) * NB + n];
            ar = fmaf(r4.x, h0, fmaf(r4.y, h1, fmaf(r4.z, h2, fmaf(r4.w, h3, ar))));
            az = fmaf(z4.x, h0, fmaf(z4.y, h1, fmaf(z4.z, h2, fmaf(z4.w, h3, az))));
            an = fmaf(n4.x, h0, fmaf(n4.y, h1, fmaf(n4.z, h2, fmaf(n4.w, h3, an))));
        }
        part[0][jl][ks][n] = ar;
        part[1][jl][ks][n] = az;
        part[2][jl][ks][n] = an;
        __syncthreads();

        if (tid < 128) {
            int jl2 = tid >> 5, n2 = tid & 31;
            int j2 = bx * 4 + jl2;
            float hr = part[0][jl2][0][n2] + part[0][jl2][1][n2] + part[0][jl2][2][n2] + part[0][jl2][3][n2] + b_hh[j2];
            float hz = part[1][jl2][0][n2] + part[1][jl2][1][n2] + part[1][jl2][2][n2] + part[1][jl2][3][n2] + b_hh[j2 + 512];
            float hn = part[2][jl2][0][n2] + part[2][jl2][1][n2] + part[2][jl2][2][n2] + part[2][jl2][3][n2] + b_hh[j2 + 1024];

            float gr = g_Git[((size_t)t * 1536 + j2) * NB + n2];
            float gz = g_Git[((size_t)t * 1536 + j2 + 512) * NB + n2];
            float gn = g_Git[((size_t)t * 1536 + j2 + 1024) * NB + n2];

            float rg_ = sigmoidf_(gr + hr);
            float zg  = sigmoidf_(gz + hz);
            float ng  = tanhf(gn + rg_ * hn);
            float hprev = hp[j2 * NB + n2];
            float hval = (1.0f - zg) * ng + zg * hprev;
            g_Hst[(size_t)(t + 1) * (HID * NB) + j2 * NB + n2] = hval;

            // bf16 A image write
            int r = t * 32 + n2;
            int btI = r >> 7, mr = r & 127, kc = j2 >> 5, cc = j2 & 31;
            g_Aimg[(size_t)(btI * 16 + kc) * 5120 + (size_t)mr * 40 + cc] = __float2bfloat16(hval);
        }

        // grid barrier: single release fence by arriving thread only
        __syncthreads();
        if (tid == 0) {
            __threadfence();
            unsigned int old = atomicAdd(&g_cnt, 1);
            if (old == NBLK - 1) {
                *((volatile unsigned int*)&g_cnt) = 0;
                __threadfence();
                atomicAdd(&g_gen, 1);
            } else {
                unsigned int cur;
                do {
                    asm volatile("ld.acquire.gpu.u32 %0, [%1];" : "=r"(cur) : "l"(&g_gen));
                } while (cur == mygen);
            }
        }
        mygen++;
        __syncthreads();
    }
}

// ---------------- emit GEMM (pure bf16 mma.sync) + fused logsumexp ----------------
// grid (bt 0..31, vt 0..196), 512 threads / 16 warps; CTA tile 128x256, K in 16 stages of 32.
// 6-deep cp.async.bulk ring (A and B images are byte-exact smem tiles).
__global__ __launch_bounds__(512, 1) void emitMMA() {
    extern __shared__ __align__(128) char dsm[];
    __shared__ float bsh[TN];
    __shared__ float redm[128][4], reds[128][4];
    __shared__ __align__(8) ull s_mbar[NRING];

    int tid = threadIdx.x, lane = tid & 31, w = tid >> 5;
    int mq = w & 3, nq = w >> 2;
    int rowBase = mq * 32, colBase = nq * 64;
    int bt = blockIdx.x, vt = blockIdx.y;
    int ro = bt * TM, vo = vt * TN;

    uint32 base = smem_u32(dsm);
    if (tid == 0) {
#pragma unroll
        for (int i = 0; i < NRING; ++i) MBAR_INIT(smem_u32(&s_mbar[i]), 1);
    }
    if (tid < TN) bsh[tid] = g_bpad[vo + tid];
    __syncthreads();
    uint32 mb[NRING];
#pragma unroll
    for (int i = 0; i < NRING; ++i) mb[i] = smem_u32(&s_mbar[i]);

    const char* srcA = (const char*)g_Aimg + (size_t)bt * 16 * ABLK;
    const char* srcB = (const char*)g_Wimg + (size_t)vt * 16 * BBLK;

    // prologue: issue stages 0..NRING-2
    if (tid == 0) {
#pragma unroll
        for (int q = 0; q < NRING - 1; ++q) {
            uint32 qb = base + (uint32)q * STG1;
            EXPECT_TX(mb[q], STG1);
            BULK(qb,        srcA + (size_t)q * ABLK, ABLK, mb[q]);
            BULK(qb + ABLK, srcB + (size_t)q * BBLK, BBLK, mb[q]);
        }
    }

    int ar = (lane & 7) + ((lane >> 3) & 1) * 8, ac = ((lane >> 4) & 1) * 8;
    int br = (lane & 7) + ((lane >> 4) & 1) * 8, bc = ((lane >> 3) & 1) * 8;
    uint32 aOff0 = (uint32)((rowBase + ar) * 80 + ac * 2);
    uint32 aOff1 = (uint32)((rowBase + 16 + ar) * 80 + ac * 2);
    uint32 bOffs[4];
#pragma unroll
    for (int np = 0; np < 4; ++np) bOffs[np] = (uint32)((colBase + np * 16 + br) * 80 + bc * 2);

    float acc[2][8][4];
#pragma unroll
    for (int mt = 0; mt < 2; ++mt)
#pragma unroll
        for (int nt = 0; nt < 8; ++nt)
#pragma unroll
            for (int c = 0; c < 4; ++c) acc[mt][nt][c] = 0.0f;

#pragma unroll 1
    for (int s = 0; s < NSTG; ++s) {
        int slot = s % NRING;
        int phase = (s / NRING) & 1;
        if (tid == 0 && s + NRING - 1 < NSTG) {
            int q = s + NRING - 1;
            int qs = q % NRING;
            uint32 qb = base + (uint32)qs * STG1;
            EXPECT_TX(mb[qs], STG1);
            BULK(qb,        srcA + (size_t)q * ABLK, ABLK, mb[qs]);
            BULK(qb + ABLK, srcB + (size_t)q * BBLK, BBLK, mb[qs]);
        }
        MBAR_WAIT(mb[slot], phase);

        uint32 bufA = base + (uint32)slot * STG1;
        uint32 bufB = bufA + ABLK;
#pragma unroll
        for (int kbi = 0; kbi < 2; ++kbi) {
            uint32 ko = (uint32)(kbi * 32);
            uint32 af[2][4];
            LDSM4(af[0], bufA + aOff0 + ko);
            LDSM4(af[1], bufA + aOff1 + ko);
#pragma unroll
            for (int np = 0; np < 4; ++np) {
                uint32 bb[4];
                LDSM4(bb, bufB + bOffs[np] + ko);
#pragma unroll
                for (int mt = 0; mt < 2; ++mt) {
                    MMA_BF16(acc[mt][2 * np + 0], af[mt], bb[0], bb[1]);
                    MMA_BF16(acc[mt][2 * np + 1], af[mt], bb[2], bb[3]);
                }
            }
        }
        __syncthreads();
    }

    // epilogue: bias + per-row max/sumexp (poly exp on FMA pipe), lane/warp/block reduce
    int g = lane >> 2, tg = lane & 3;
#pragma unroll
    for (int mt = 0; mt < 2; ++mt) {
#pragma unroll
        for (int h = 0; h < 2; ++h) {
            float x[16], m = -1e30f;
#pragma unroll
            for (int nt = 0; nt < 8; ++nt) {
#pragma unroll
                for (int c = 0; c < 2; ++c) {
                    float v = acc[mt][nt][2 * h + c] + bsh[colBase + nt * 8 + 2 * tg + c];
                    x[nt * 2 + c] = v;
                    m = fmaxf(m, v);
                }
            }
            float ssum = 0.0f;
#pragma unroll
            for (int i = 0; i < 16; ++i) ssum += fexp(x[i] - m);
#pragma unroll
            for (int o = 1; o <= 2; o <<= 1) {
                float m2 = __shfl_xor_sync(0xffffffffu, m, o);
                float s2 = __shfl_xor_sync(0xffffffffu, ssum, o);
                lse_combine(m, ssum, m2, s2);
            }
            if (tg == 0) {
                int rl = rowBase + mt * 16 + g + h * 8;
                redm[rl][nq] = m;
                reds[rl][nq] = ssum;
            }
        }
    }
    __syncthreads();
    if (tid < 128) {
        float M = -1e30f, S = 0.0f;
#pragma unroll
        for (int q = 0; q < 4; ++q) lse_combine(M, S, redm[tid][q], reds[tid][q]);
        int row = ro + tid;
        g_Pm[(size_t)vt * RPAD + row] = M;
        g_Ps[(size_t)vt * RPAD + row] = S;
    }
}

// ---------------- target logits ----------------
__global__ void tlogK(const int* __restrict__ words,
                      const float* __restrict__ emit_W,
                      const float* __restrict__ emit_b) {
    int gtid = blockIdx.x * blockDim.x + threadIdx.x;
    int warp = gtid >> 5;
    int lane = threadIdx.x & 31;
    if (warp >= NROWS) return;
    int t = warp >> 5, n = warp & 31;
    int tgt = words[n * TT + t + 1];
    const float* h = g_Hst + (size_t)(t + 1) * (HID * NB);
    const float* wv = emit_W + (size_t)tgt * 512;
    float s = 0.0f;
    for (int k = lane; k < 512; k += 32) s += h[k * NB + n] * wv[k];
#pragma unroll
    for (int o = 16; o; o >>= 1) s += __shfl_xor_sync(0xffffffffu, s, o);
    if (lane == 0) g_Tlog[warp] = s + emit_b[tgt];
}

// ---------------- finalize ----------------
__global__ void finK(float* __restrict__ out) {
    int n = blockIdx.x;
    int tid = threadIdx.x;
    __shared__ float sh[128];
    float v = 0.0f;
    if (tid < NSTEP) {
        int r = tid * NB + n;
        float M = -1e30f, S = 0.0f;
        for (int c = 0; c < NVT2; ++c)
            lse_combine(M, S, g_Pm[(size_t)c * RPAD + r], g_Ps[(size_t)c * RPAD + r]);
        v = g_Tlog[r] - (M + logf(S));
    }
    sh[tid] = v;
    __syncthreads();
    for (int o = 64; o; o >>= 1) { if (tid < o) sh[tid] += sh[tid + o]; __syncthreads(); }
    if (tid == 0) out[n] = sh[0] / (float)NSTEP;
}

// ---------------- h_final ----------------
__global__ void hfinK(float* __restrict__ out) {
    int idx = blockIdx.x * blockDim.x + threadIdx.x;
    int n = idx >> 9, k = idx & 511;
    out[32 + idx] = g_Hst[(size_t)127 * (HID * NB) + k * NB + n];
}

// ---------------- launch ----------------
extern "C" void kernel_launch(void* const* d_in, const int* in_sizes, int n_in,
                              void* d_out, int out_size) {
    const int*   words  = (const int*)d_in[0];
    const float* h0     = (const float*)d_in[1];
    const float* embW   = (const float*)d_in[2];
    const float* W_ih   = (const float*)d_in[3];
    const float* W_hh   = (const float*)d_in[4];
    const float* b_ih   = (const float*)d_in[5];
    const float* b_hh   = (const float*)d_in[6];
    const float* emit_W = (const float*)d_in[7];
    const float* emit_b = (const float*)d_in[8];
    float* out = (float*)d_out;

    static int configured = 0;
    if (!configured) {
        cudaFuncSetAttribute(emitMMA, cudaFuncAttributeMaxDynamicSharedMemorySize, DYNB);
        configured = 1;
    }

    // 1: merged prep
    prepAll<<<(int)((PREP_TOTAL + 255) / 256), 256>>>(emit_W, emit_b, h0, W_ih);

    // 2: input-gate projections
    giK<<<dim3(3, 254), 256>>>(words, embW, b_ih);

    // 3: persistent GRU recurrence (fuses bf16 A-image conversion)
    gruPersist<<<NBLK, 512>>>(W_hh, b_hh);

    // 4: emit GEMM + logsumexp  (<-- profiled launch)
    emitMMA<<<dim3(32, NVT2), 512, DYNB>>>();

    tlogK<<<508, 256>>>(words, emit_W, emit_b);
    finK<<<32, 128>>>(out);
    hfinK<<<64, 256>>>(out);
}

// round 14
// speedup vs baseline: 1.1791x; 1.1791x over previous
#include <cuda_runtime.h>
#include <cuda_bf16.h>
#include <math.h>

typedef unsigned long long ull;
typedef unsigned int uint32;

#define V_VOCAB 50257
#define VP2     50432          // 197 tiles * 256
#define NVT2    197
#define HID     512
#define NB      32
#define TT      128
#define NSTEP   127
#define NROWS   4064
#define RPAD    4096           // 32 row tiles * 128
#define NBLK    128            // persistent GRU blocks

// emit tile: M=128 x N=256, K=512 in 16 stages of 32; 6-deep bulk ring
#define TM      128
#define TN      256
#define NSTG    16
#define ABLK    10240          // 128 rows * 80B
#define BBLK    20480          // 256 rows * 80B
#define STG1    (ABLK + BBLK)  // 30720
#define NRING   6
#define DYNB    (NRING * STG1) // 184320

// ---------------- static device scratch ----------------
__device__ __align__(16) float g_Wt_ih[512 * 1536];               // W_ih transposed [k][j]
__device__ __align__(16) float g_Git[(size_t)NSTEP * 1536 * NB];  // gi, [t][j][n]
__device__ __align__(16) float g_Hst[128 * HID * NB];             // hidden states [t][k][n]
__device__ __align__(16) float g_bpad[VP2];                       // emit_b padded with -1e30
// B image: [vt][kc 16][vrow 256][40 bf16] — byte-exact smem tile, 80B rows
__device__ __align__(16) __nv_bfloat16 g_Wimg[(size_t)NVT2 * 16 * 256 * 40];
// A image: [bt 32][kc 16][mrow 128][40 bf16]
__device__ __align__(16) __nv_bfloat16 g_Aimg[(size_t)32 * 16 * 128 * 40];
__device__ float g_Pm[(size_t)NVT2 * RPAD];
__device__ float g_Ps[(size_t)NVT2 * RPAD];
__device__ float g_Tlog[NROWS];
__device__ unsigned int g_cnt = 0;   // grid barrier arrivals (self-resetting)
__device__ unsigned int g_gen = 0;   // grid barrier generation (monotonic)

__device__ __forceinline__ float sigmoidf_(float x) { return 1.0f / (1.0f + expf(-x)); }

__device__ __forceinline__ void lse_combine(float& M, float& S, float m2, float s2) {
    if (m2 > M) { S = S * expf(M - m2) + s2; M = m2; }
    else        { S += s2 * expf(m2 - M); }
}

// fast exp for x <= 0 on the FMA pipe (deg-5, rint-centered; rel err ~4e-7)
__device__ __forceinline__ float fexp(float x) {
    x = fmaxf(x, -20.0f);
    float t = x * 1.4426950408889634f;
    float fi = rintf(t);
    float f = t - fi;
    float p = 0.0013333558f;
    p = fmaf(p, f, 0.0096181291f);
    p = fmaf(p, f, 0.0555041087f);
    p = fmaf(p, f, 0.2402265070f);
    p = fmaf(p, f, 0.6931471806f);
    p = fmaf(p, f, 1.0f);
    int e = (int)fi;
    float s = __int_as_float((e + 127) << 23);
    return p * s;
}

// ---------------- f32x2 helpers ----------------
__device__ __forceinline__ ull pack2(float lo, float hi) {
    ull r; asm("mov.b64 %0, {%1, %2};" : "=l"(r) : "f"(lo), "f"(hi)); return r;
}
__device__ __forceinline__ float2 unpack2(ull v) {
    float2 f; asm("mov.b64 {%0, %1}, %2;" : "=f"(f.x), "=f"(f.y) : "l"(v)); return f;
}
__device__ __forceinline__ void ffma2(ull& acc, ull a, ull b) {
    asm("fma.rn.f32x2 %0, %1, %2, %0;" : "+l"(acc) : "l"(a), "l"(b));
}

// ---------------- mma / bulk helpers ----------------
__device__ __forceinline__ uint32 smem_u32(const void* p) {
    return (uint32)__cvta_generic_to_shared(p);
}
#define LDSM4(R, addr) asm volatile( \
    "ldmatrix.sync.aligned.m8n8.x4.shared.b16 {%0,%1,%2,%3}, [%4];" \
    : "=r"((R)[0]), "=r"((R)[1]), "=r"((R)[2]), "=r"((R)[3]) : "r"(addr))
#define MMA_BF16(D, A, B0, B1) asm volatile( \
    "mma.sync.aligned.m16n8k16.row.col.f32.bf16.bf16.f32 " \
    "{%0,%1,%2,%3}, {%4,%5,%6,%7}, {%8,%9}, {%0,%1,%2,%3};" \
    : "+f"((D)[0]), "+f"((D)[1]), "+f"((D)[2]), "+f"((D)[3]) \
    : "r"((A)[0]), "r"((A)[1]), "r"((A)[2]), "r"((A)[3]), "r"(B0), "r"(B1))
#define MBAR_INIT(mb, cnt) asm volatile( \
    "mbarrier.init.shared.b64 [%0], %1;" :: "r"(mb), "r"((uint32)(cnt)) : "memory")
#define EXPECT_TX(mb, bytes) asm volatile( \
    "mbarrier.arrive.expect_tx.shared.b64 _, [%0], %1;" :: "r"(mb), "r"((uint32)(bytes)) : "memory")
#define BULK(dst, src, bytes, mb) asm volatile( \
    "cp.async.bulk.shared::cluster.global.mbarrier::complete_tx::bytes [%0], [%1], %2, [%3];" \
    :: "r"(dst), "l"(src), "r"((uint32)(bytes)), "r"(mb) : "memory")
#define MBAR_WAIT(mb, par) do { \
    uint32 _mb = (mb); uint32 _p = (par); uint32 _done; \
    asm volatile("{\n\t.reg .pred p;\n\t" \
        "mbarrier.try_wait.parity.acquire.cta.shared::cta.b64 p, [%1], %2;\n\t" \
        "selp.b32 %0, 1, 0, p;\n\t}" : "=r"(_done) : "r"(_mb), "r"(_p) : "memory"); \
    if (!_done) { \
        asm volatile("{\n\t.reg .pred P1;\n\t" \
            "WL_%=:\n\t" \
            "mbarrier.try_wait.parity.acquire.cta.shared::cta.b64 P1, [%0], %1, 0x989680;\n\t" \
            "@P1 bra.uni WD_%=;\n\t" \
            "bra.uni WL_%=;\n\t" \
            "WD_%=:\n\t}" :: "r"(_mb), "r"(_p) : "memory"); \
    } \
} while (0)

// ---------------- prep 1: B image build, no 64-bit division ----------------
// grid (NVT2*16, 32), block 320 = 8 vr-rows x 40 cols
__global__ __launch_bounds__(320) void convWimg(const float* __restrict__ emit_W) {
    int blk = blockIdx.x;            // vt*16 + kc
    int vt = blk >> 4, kc = blk & 15;
    int tid = threadIdx.x;
    int c = tid % 40, rr = tid / 40; // 32-bit const div: cheap
    int vr = blockIdx.y * 8 + rr;
    int v = vt * 256 + vr, k = kc * 32 + c;
    float x = (c < 32 && v < V_VOCAB) ? emit_W[(size_t)v * 512 + k] : 0.0f;
    g_Wimg[(size_t)blk * 10240 + vr * 40 + c] = __float2bfloat16(x);
}

// ---------------- prep 2: bpad + initH + W_ih transpose (32-bit indexing) ----------------
#define PM_TOTAL (VP2 + 16384 + 786432)
__global__ __launch_bounds__(256) void prepMisc(const float* __restrict__ emit_b,
                                                const float* __restrict__ h0,
                                                const float* __restrict__ W_ih) {
    int idx = blockIdx.x * 256 + threadIdx.x;
    if (idx < VP2) {
        g_bpad[idx] = (idx < V_VOCAB) ? emit_b[idx] : -1e30f;
        return;
    }
    idx -= VP2;
    if (idx < 16384) {
        int n = idx >> 9, k = idx & 511;
        g_Hst[k * NB + n] = h0[idx];
        return;
    }
    idx -= 16384;
    if (idx < 786432) {
        int k = idx / 1536, j = idx % 1536;   // 32-bit const div
        g_Wt_ih[idx] = W_ih[(size_t)j * 512 + k];
    }
}

// ---------------- gi GEMM ----------------
__global__ __launch_bounds__(256) void giK(const int* __restrict__ words,
                                           const float* __restrict__ embW,
                                           const float* __restrict__ b_ih) {
    int jc = blockIdx.x, rg = blockIdx.y;
    int tid = threadIdx.x, tx = tid & 63, ty = tid >> 6;
    __shared__ float ash[16 * 514];
    int rbase = rg * 16;
    for (int idx = tid; idx < 8192; idx += 256) {
        int i = idx >> 9, k = idx & 511;
        int r = rbase + i;
        int w = words[(r & 31) * TT + (r >> 5)];
        ash[i * 514 + k] = embW[(size_t)w * 512 + k];
    }
    __syncthreads();

    int j0 = jc * 512 + tx * 8;
    ull acc[4][4];
#pragma unroll
    for (int a = 0; a < 4; ++a)
#pragma unroll
        for (int b = 0; b < 4; ++b) acc[a][b] = 0ull;

    const float* wp = g_Wt_ih + j0;
    int rb = ty * 4;
#pragma unroll 4
    for (int k = 0; k < 512; ++k) {
        float4 wa = *(const float4*)(wp);
        float4 wb = *(const float4*)(wp + 4);
        wp += 1536;
        ull b0 = pack2(wa.x, wa.y), b1 = pack2(wa.z, wa.w);
        ull b2 = pack2(wb.x, wb.y), b3 = pack2(wb.z, wb.w);
#pragma unroll
        for (int ri = 0; ri < 4; ++ri) {
            float h = ash[(rb + ri) * 514 + k];
            ull a2 = pack2(h, h);
            ffma2(acc[ri][0], a2, b0);
            ffma2(acc[ri][1], a2, b1);
            ffma2(acc[ri][2], a2, b2);
            ffma2(acc[ri][3], a2, b3);
        }
    }

    int t = rbase >> 5;
#pragma unroll
    for (int ri = 0; ri < 4; ++ri) {
        int r = rbase + rb + ri;
        int n = r & 31;
#pragma unroll
        for (int p = 0; p < 4; ++p) {
            float2 l = unpack2(acc[ri][p]);
            int j = j0 + 2 * p;
            g_Git[((size_t)t * 1536 + j) * NB + n]     = l.x + b_ih[j];
            g_Git[((size_t)t * 1536 + j + 1) * NB + n] = l.y + b_ih[j + 1];
        }
    }
}

// ---------------- persistent GRU: FFMA2 dot + Git prefetch + cheap grid barrier ----------------
__global__ __launch_bounds__(512) void gruPersist(const float* __restrict__ W_hh,
                                                  const float* __restrict__ b_hh) {
    __shared__ float part[3][4][4][32];
    int tid = threadIdx.x;
    int n = tid & 31, ks = (tid >> 5) & 3, jl = tid >> 7;
    int bx = blockIdx.x;
    int j = bx * 4 + jl;
    unsigned int mygen = g_gen;

    int kb = ks * 128;
    const float* wr = W_hh + (size_t)j * 512 + kb;
    const float* wz = wr + 512 * 512;
    const float* wn = wz + 512 * 512;

    // phase-2 thread mapping (tid < 128)
    int jl2 = tid >> 5, n2 = tid & 31;
    int j2 = bx * 4 + jl2;

    for (int t = 0; t < NSTEP; ++t) {
        const float* hp = g_Hst + (size_t)t * (HID * NB);
        const float* hb = hp + kb * NB;

        // prefetch gate inputs early (hide L2 latency behind the dot loop)
        float gr = 0.f, gz = 0.f, gn = 0.f, hprev = 0.f;
        if (tid < 128) {
            gr = g_Git[((size_t)t * 1536 + j2) * NB + n2];
            gz = g_Git[((size_t)t * 1536 + j2 + 512) * NB + n2];
            gn = g_Git[((size_t)t * 1536 + j2 + 1024) * NB + n2];
            hprev = hp[j2 * NB + n2];
        }

        ull ar2 = 0ull, az2 = 0ull, an2 = 0ull;
        ull br2 = 0ull, bz2 = 0ull, bn2 = 0ull;
#pragma unroll 8
        for (int k = 0; k < 128; k += 4) {
            float4 r4 = *(const float4*)(wr + k);
            float4 z4 = *(const float4*)(wz + k);
            float4 n4 = *(const float4*)(wn + k);
            float h0 = hb[(k + 0) * NB + n];
            float h1 = hb[(k + 1) * NB + n];
            float h2 = hb[(k + 2) * NB + n];
            float h3 = hb[(k + 3) * NB + n];
            ull hA = pack2(h0, h1), hB = pack2(h2, h3);
            ffma2(ar2, hA, pack2(r4.x, r4.y));
            ffma2(br2, hB, pack2(r4.z, r4.w));
            ffma2(az2, hA, pack2(z4.x, z4.y));
            ffma2(bz2, hB, pack2(z4.z, z4.w));
            ffma2(an2, hA, pack2(n4.x, n4.y));
            ffma2(bn2, hB, pack2(n4.z, n4.w));
        }
        {
            float2 u, v;
            u = unpack2(ar2); v = unpack2(br2); part[0][jl][ks][n] = u.x + u.y + v.x + v.y;
            u = unpack2(az2); v = unpack2(bz2); part[1][jl][ks][n] = u.x + u.y + v.x + v.y;
            u = unpack2(an2); v = unpack2(bn2); part[2][jl][ks][n] = u.x + u.y + v.x + v.y;
        }
        __syncthreads();

        if (tid < 128) {
            float hr = part[0][jl2][0][n2] + part[0][jl2][1][n2] + part[0][jl2][2][n2] + part[0][jl2][3][n2] + b_hh[j2];
            float hz = part[1][jl2][0][n2] + part[1][jl2][1][n2] + part[1][jl2][2][n2] + part[1][jl2][3][n2] + b_hh[j2 + 512];
            float hn = part[2][jl2][0][n2] + part[2][jl2][1][n2] + part[2][jl2][2][n2] + part[2][jl2][3][n2] + b_hh[j2 + 1024];

            float rg_ = sigmoidf_(gr + hr);
            float zg  = sigmoidf_(gz + hz);
            float ng  = tanhf(gn + rg_ * hn);
            float hval = (1.0f - zg) * ng + zg * hprev;
            g_Hst[(size_t)(t + 1) * (HID * NB) + j2 * NB + n2] = hval;

            // bf16 A image write
            int r = t * 32 + n2;
            int btI = r >> 7, mr = r & 127, kc = j2 >> 5, cc = j2 & 31;
            g_Aimg[(size_t)(btI * 16 + kc) * 5120 + (size_t)mr * 40 + cc] = __float2bfloat16(hval);
        }

        // grid barrier: single release fence by arriving thread only
        __syncthreads();
        if (tid == 0) {
            __threadfence();
            unsigned int old = atomicAdd(&g_cnt, 1);
            if (old == NBLK - 1) {
                *((volatile unsigned int*)&g_cnt) = 0;
                __threadfence();
                atomicAdd(&g_gen, 1);
            } else {
                unsigned int cur;
                do {
                    asm volatile("ld.acquire.gpu.u32 %0, [%1];" : "=r"(cur) : "l"(&g_gen));
                } while (cur == mygen);
            }
        }
        mygen++;
        __syncthreads();
    }
}

// ---------------- emit GEMM (pure bf16 mma.sync) + fused logsumexp ----------------
__global__ __launch_bounds__(512, 1) void emitMMA() {
    extern __shared__ __align__(128) char dsm[];
    __shared__ float bsh[TN];
    __shared__ float redm[128][4], reds[128][4];
    __shared__ __align__(8) ull s_mbar[NRING];

    int tid = threadIdx.x, lane = tid & 31, w = tid >> 5;
    int mq = w & 3, nq = w >> 2;
    int rowBase = mq * 32, colBase = nq * 64;
    int bt = blockIdx.x, vt = blockIdx.y;
    int ro = bt * TM, vo = vt * TN;

    uint32 base = smem_u32(dsm);
    if (tid == 0) {
#pragma unroll
        for (int i = 0; i < NRING; ++i) MBAR_INIT(smem_u32(&s_mbar[i]), 1);
    }
    if (tid < TN) bsh[tid] = g_bpad[vo + tid];
    __syncthreads();
    uint32 mb[NRING];
#pragma unroll
    for (int i = 0; i < NRING; ++i) mb[i] = smem_u32(&s_mbar[i]);

    const char* srcA = (const char*)g_Aimg + (size_t)bt * 16 * ABLK;
    const char* srcB = (const char*)g_Wimg + (size_t)vt * 16 * BBLK;

    if (tid == 0) {
#pragma unroll
        for (int q = 0; q < NRING - 1; ++q) {
            uint32 qb = base + (uint32)q * STG1;
            EXPECT_TX(mb[q], STG1);
            BULK(qb,        srcA + (size_t)q * ABLK, ABLK, mb[q]);
            BULK(qb + ABLK, srcB + (size_t)q * BBLK, BBLK, mb[q]);
        }
    }

    int ar = (lane & 7) + ((lane >> 3) & 1) * 8, ac = ((lane >> 4) & 1) * 8;
    int br = (lane & 7) + ((lane >> 4) & 1) * 8, bc = ((lane >> 3) & 1) * 8;
    uint32 aOff0 = (uint32)((rowBase + ar) * 80 + ac * 2);
    uint32 aOff1 = (uint32)((rowBase + 16 + ar) * 80 + ac * 2);
    uint32 bOffs[4];
#pragma unroll
    for (int np = 0; np < 4; ++np) bOffs[np] = (uint32)((colBase + np * 16 + br) * 80 + bc * 2);

    float acc[2][8][4];
#pragma unroll
    for (int mt = 0; mt < 2; ++mt)
#pragma unroll
        for (int nt = 0; nt < 8; ++nt)
#pragma unroll
            for (int c = 0; c < 4; ++c) acc[mt][nt][c] = 0.0f;

#pragma unroll 1
    for (int s = 0; s < NSTG; ++s) {
        int slot = s % NRING;
        int phase = (s / NRING) & 1;
        if (tid == 0 && s + NRING - 1 < NSTG) {
            int q = s + NRING - 1;
            int qs = q % NRING;
            uint32 qb = base + (uint32)qs * STG1;
            EXPECT_TX(mb[qs], STG1);
            BULK(qb,        srcA + (size_t)q * ABLK, ABLK, mb[qs]);
            BULK(qb + ABLK, srcB + (size_t)q * BBLK, BBLK, mb[qs]);
        }
        MBAR_WAIT(mb[slot], phase);

        uint32 bufA = base + (uint32)slot * STG1;
        uint32 bufB = bufA + ABLK;
#pragma unroll
        for (int kbi = 0; kbi < 2; ++kbi) {
            uint32 ko = (uint32)(kbi * 32);
            uint32 af[2][4];
            LDSM4(af[0], bufA + aOff0 + ko);
            LDSM4(af[1], bufA + aOff1 + ko);
#pragma unroll
            for (int np = 0; np < 4; ++np) {
                uint32 bb[4];
                LDSM4(bb, bufB + bOffs[np] + ko);
#pragma unroll
                for (int mt = 0; mt < 2; ++mt) {
                    MMA_BF16(acc[mt][2 * np + 0], af[mt], bb[0], bb[1]);
                    MMA_BF16(acc[mt][2 * np + 1], af[mt], bb[2], bb[3]);
                }
            }
        }
        __syncthreads();
    }

    int g = lane >> 2, tg = lane & 3;
#pragma unroll
    for (int mt = 0; mt < 2; ++mt) {
#pragma unroll
        for (int h = 0; h < 2; ++h) {
            float x[16], m = -1e30f;
#pragma unroll
            for (int nt = 0; nt < 8; ++nt) {
#pragma unroll
                for (int c = 0; c < 2; ++c) {
                    float v = acc[mt][nt][2 * h + c] + bsh[colBase + nt * 8 + 2 * tg + c];
                    x[nt * 2 + c] = v;
                    m = fmaxf(m, v);
                }
            }
            float ssum = 0.0f;
#pragma unroll
            for (int i = 0; i < 16; ++i) ssum += fexp(x[i] - m);
#pragma unroll
            for (int o = 1; o <= 2; o <<= 1) {
                float m2 = __shfl_xor_sync(0xffffffffu, m, o);
                float s2 = __shfl_xor_sync(0xffffffffu, ssum, o);
                lse_combine(m, ssum, m2, s2);
            }
            if (tg == 0) {
                int rl = rowBase + mt * 16 + g + h * 8;
                redm[rl][nq] = m;
                reds[rl][nq] = ssum;
            }
        }
    }
    __syncthreads();
    if (tid < 128) {
        float M = -1e30f, S = 0.0f;
#pragma unroll
        for (int q = 0; q < 4; ++q) lse_combine(M, S, redm[tid][q], reds[tid][q]);
        int row = ro + tid;
        g_Pm[(size_t)vt * RPAD + row] = M;
        g_Ps[(size_t)vt * RPAD + row] = S;
    }
}

// ---------------- target logits ----------------
__global__ void tlogK(const int* __restrict__ words,
                      const float* __restrict__ emit_W,
                      const float* __restrict__ emit_b) {
    int gtid = blockIdx.x * blockDim.x + threadIdx.x;
    int warp = gtid >> 5;
    int lane = threadIdx.x & 31;
    if (warp >= NROWS) return;
    int t = warp >> 5, n = warp & 31;
    int tgt = words[n * TT + t + 1];
    const float* h = g_Hst + (size_t)(t + 1) * (HID * NB);
    const float* wv = emit_W + (size_t)tgt * 512;
    float s = 0.0f;
    for (int k = lane; k < 512; k += 32) s += h[k * NB + n] * wv[k];
#pragma unroll
    for (int o = 16; o; o >>= 1) s += __shfl_xor_sync(0xffffffffu, s, o);
    if (lane == 0) g_Tlog[warp] = s + emit_b[tgt];
}

// ---------------- finalize ----------------
__global__ void finK(float* __restrict__ out) {
    int n = blockIdx.x;
    int tid = threadIdx.x;
    __shared__ float sh[128];
    float v = 0.0f;
    if (tid < NSTEP) {
        int r = tid * NB + n;
        float M = -1e30f, S = 0.0f;
        for (int c = 0; c < NVT2; ++c)
            lse_combine(M, S, g_Pm[(size_t)c * RPAD + r], g_Ps[(size_t)c * RPAD + r]);
        v = g_Tlog[r] - (M + logf(S));
    }
    sh[tid] = v;
    __syncthreads();
    for (int o = 64; o; o >>= 1) { if (tid < o) sh[tid] += sh[tid + o]; __syncthreads(); }
    if (tid == 0) out[n] = sh[0] / (float)NSTEP;
}

// ---------------- h_final ----------------
__global__ void hfinK(float* __restrict__ out) {
    int idx = blockIdx.x * blockDim.x + threadIdx.x;
    int n = idx >> 9, k = idx & 511;
    out[32 + idx] = g_Hst[(size_t)127 * (HID * NB) + k * NB + n];
}

// ---------------- launch ----------------
extern "C" void kernel_launch(void* const* d_in, const int* in_sizes, int n_in,
                              void* d_out, int out_size) {
    const int*   words  = (const int*)d_in[0];
    const float* h0     = (const float*)d_in[1];
    const float* embW   = (const float*)d_in[2];
    const float* W_ih   = (const float*)d_in[3];
    const float* W_hh   = (const float*)d_in[4];
    const float* b_ih   = (const float*)d_in[5];
    const float* b_hh   = (const float*)d_in[6];
    const float* emit_W = (const float*)d_in[7];
    const float* emit_b = (const float*)d_in[8];
    float* out = (float*)d_out;

    static int configured = 0;
    if (!configured) {
        cudaFuncSetAttribute(emitMMA, cudaFuncAttributeMaxDynamicSharedMemorySize, DYNB);
        configured = 1;
    }

    // 1: B image build (no 64-bit div)
    convWimg<<<dim3(NVT2 * 16, 32), 320>>>(emit_W);

    // 2: bpad + initH + W_ih transpose
    prepMisc<<<(PM_TOTAL + 255) / 256, 256>>>(emit_b, h0, W_ih);

    // 3: input-gate projections
    giK<<<dim3(3, 254), 256>>>(words, embW, b_ih);

    // 4: persistent GRU recurrence  (<-- profiled launch this round)
    gruPersist<<<NBLK, 512>>>(W_hh, b_hh);

    // 5: emit GEMM + logsumexp
    emitMMA<<<dim3(32, NVT2), 512, DYNB>>>();

    tlogK<<<508, 256>>>(words, emit_W, emit_b);
    finK<<<32, 128>>>(out);
    hfinK<<<64, 256>>>(out);
}

// round 15
// speedup vs baseline: 1.7352x; 1.4716x over previous
#include <cuda_runtime.h>
#include <cuda_bf16.h>
#include <math.h>

typedef unsigned long long ull;
typedef unsigned int uint32;

#define V_VOCAB 50257
#define VP2     50432          // 197 tiles * 256
#define NVT2    197
#define HID     512
#define NB      32
#define TT      128
#define NSTEP   127
#define NROWS   4064
#define RPAD    4096           // 32 row tiles * 128
#define NBLK    128            // persistent GRU blocks

// emit tile: M=128 x N=256, K=512 in 16 stages of 32; 6-deep bulk ring
#define TM      128
#define TN      256
#define NSTG    16
#define ABLK    10240          // 128 rows * 80B
#define BBLK    20480          // 256 rows * 80B
#define STG1    (ABLK + BBLK)  // 30720
#define NRING   6
#define DYNB    (NRING * STG1) // 184320

// gru dynamic smem: Wsh 24KB + hsh 64KB
#define GW_BYTES 24576
#define GH_BYTES 65536
#define GDYN     (GW_BYTES + GH_BYTES)   // 90112

// ---------------- static device scratch ----------------
__device__ __align__(16) float g_Wt_ih[512 * 1536];               // W_ih transposed [k][j]
__device__ __align__(16) float g_Git[(size_t)NSTEP * 1536 * NB];  // gi, [t][j][n]
__device__ __align__(16) float g_Hst[128 * HID * NB];             // hidden states [t][k][n]
__device__ __align__(16) float g_bpad[VP2];                       // emit_b padded with -1e30
// B image: [vt][kc 16][vrow 256][40 bf16] — byte-exact smem tile, 80B rows
__device__ __align__(16) __nv_bfloat16 g_Wimg[(size_t)NVT2 * 16 * 256 * 40];
// A image: [bt 32][kc 16][mrow 128][40 bf16]
__device__ __align__(16) __nv_bfloat16 g_Aimg[(size_t)32 * 16 * 128 * 40];
__device__ float g_Pm[(size_t)NVT2 * RPAD];
__device__ float g_Ps[(size_t)NVT2 * RPAD];
__device__ float g_Tlog[NROWS];
__device__ unsigned int g_cnt8[8];   // two-level arrivals (self-resetting)
__device__ unsigned int g_top = 0;
__device__ unsigned int g_gen = 0;   // generation (monotonic)

__device__ __forceinline__ float sigmoidf_(float x) { return 1.0f / (1.0f + expf(-x)); }

__device__ __forceinline__ void lse_combine(float& M, float& S, float m2, float s2) {
    if (m2 > M) { S = S * expf(M - m2) + s2; M = m2; }
    else        { S += s2 * expf(m2 - M); }
}

// fast exp for x <= 0 on the FMA pipe (deg-5, rint-centered; rel err ~4e-7)
__device__ __forceinline__ float fexp(float x) {
    x = fmaxf(x, -20.0f);
    float t = x * 1.4426950408889634f;
    float fi = rintf(t);
    float f = t - fi;
    float p = 0.0013333558f;
    p = fmaf(p, f, 0.0096181291f);
    p = fmaf(p, f, 0.0555041087f);
    p = fmaf(p, f, 0.2402265070f);
    p = fmaf(p, f, 0.6931471806f);
    p = fmaf(p, f, 1.0f);
    int e = (int)fi;
    float s = __int_as_float((e + 127) << 23);
    return p * s;
}

// ---------------- f32x2 helpers ----------------
__device__ __forceinline__ ull pack2(float lo, float hi) {
    ull r; asm("mov.b64 %0, {%1, %2};" : "=l"(r) : "f"(lo), "f"(hi)); return r;
}
__device__ __forceinline__ float2 unpack2(ull v) {
    float2 f; asm("mov.b64 {%0, %1}, %2;" : "=f"(f.x), "=f"(f.y) : "l"(v)); return f;
}
__device__ __forceinline__ void ffma2(ull& acc, ull a, ull b) {
    asm("fma.rn.f32x2 %0, %1, %2, %0;" : "+l"(acc) : "l"(a), "l"(b));
}

// ---------------- mma / bulk helpers ----------------
__device__ __forceinline__ uint32 smem_u32(const void* p) {
    return (uint32)__cvta_generic_to_shared(p);
}
#define LDSM4(R, addr) asm volatile( \
    "ldmatrix.sync.aligned.m8n8.x4.shared.b16 {%0,%1,%2,%3}, [%4];" \
    : "=r"((R)[0]), "=r"((R)[1]), "=r"((R)[2]), "=r"((R)[3]) : "r"(addr))
#define MMA_BF16(D, A, B0, B1) asm volatile( \
    "mma.sync.aligned.m16n8k16.row.col.f32.bf16.bf16.f32 " \
    "{%0,%1,%2,%3}, {%4,%5,%6,%7}, {%8,%9}, {%0,%1,%2,%3};" \
    : "+f"((D)[0]), "+f"((D)[1]), "+f"((D)[2]), "+f"((D)[3]) \
    : "r"((A)[0]), "r"((A)[1]), "r"((A)[2]), "r"((A)[3]), "r"(B0), "r"(B1))
#define MBAR_INIT(mb, cnt) asm volatile( \
    "mbarrier.init.shared.b64 [%0], %1;" :: "r"(mb), "r"((uint32)(cnt)) : "memory")
#define EXPECT_TX(mb, bytes) asm volatile( \
    "mbarrier.arrive.expect_tx.shared.b64 _, [%0], %1;" :: "r"(mb), "r"((uint32)(bytes)) : "memory")
#define BULK(dst, src, bytes, mb) asm volatile( \
    "cp.async.bulk.shared::cluster.global.mbarrier::complete_tx::bytes [%0], [%1], %2, [%3];" \
    :: "r"(dst), "l"(src), "r"((uint32)(bytes)), "r"(mb) : "memory")
#define MBAR_WAIT(mb, par) do { \
    uint32 _mb = (mb); uint32 _p = (par); uint32 _done; \
    asm volatile("{\n\t.reg .pred p;\n\t" \
        "mbarrier.try_wait.parity.acquire.cta.shared::cta.b64 p, [%1], %2;\n\t" \
        "selp.b32 %0, 1, 0, p;\n\t}" : "=r"(_done) : "r"(_mb), "r"(_p) : "memory"); \
    if (!_done) { \
        asm volatile("{\n\t.reg .pred P1;\n\t" \
            "WL_%=:\n\t" \
            "mbarrier.try_wait.parity.acquire.cta.shared::cta.b64 P1, [%0], %1, 0x989680;\n\t" \
            "@P1 bra.uni WD_%=;\n\t" \
            "bra.uni WL_%=;\n\t" \
            "WD_%=:\n\t}" :: "r"(_mb), "r"(_p) : "memory"); \
    } \
} while (0)

// ---------------- prep 1: B image build, no 64-bit division ----------------
__global__ __launch_bounds__(320) void convWimg(const float* __restrict__ emit_W) {
    int blk = blockIdx.x;            // vt*16 + kc
    int vt = blk >> 4, kc = blk & 15;
    int tid = threadIdx.x;
    int c = tid % 40, rr = tid / 40;
    int vr = blockIdx.y * 8 + rr;
    int v = vt * 256 + vr, k = kc * 32 + c;
    float x = (c < 32 && v < V_VOCAB) ? emit_W[(size_t)v * 512 + k] : 0.0f;
    g_Wimg[(size_t)blk * 10240 + vr * 40 + c] = __float2bfloat16(x);
}

// ---------------- prep 2: bpad + initH + W_ih transpose ----------------
#define PM_TOTAL (VP2 + 16384 + 786432)
__global__ __launch_bounds__(256) void prepMisc(const float* __restrict__ emit_b,
                                                const float* __restrict__ h0,
                                                const float* __restrict__ W_ih) {
    int idx = blockIdx.x * 256 + threadIdx.x;
    if (idx < VP2) {
        g_bpad[idx] = (idx < V_VOCAB) ? emit_b[idx] : -1e30f;
        return;
    }
    idx -= VP2;
    if (idx < 16384) {
        int n = idx >> 9, k = idx & 511;
        g_Hst[k * NB + n] = h0[idx];
        return;
    }
    idx -= 16384;
    if (idx < 786432) {
        int k = idx / 1536, j = idx % 1536;
        g_Wt_ih[idx] = W_ih[(size_t)j * 512 + k];
    }
}

// ---------------- gi GEMM ----------------
__global__ __launch_bounds__(256) void giK(const int* __restrict__ words,
                                           const float* __restrict__ embW,
                                           const float* __restrict__ b_ih) {
    int jc = blockIdx.x, rg = blockIdx.y;
    int tid = threadIdx.x, tx = tid & 63, ty = tid >> 6;
    __shared__ float ash[16 * 514];
    int rbase = rg * 16;
    for (int idx = tid; idx < 8192; idx += 256) {
        int i = idx >> 9, k = idx & 511;
        int r = rbase + i;
        int w = words[(r & 31) * TT + (r >> 5)];
        ash[i * 514 + k] = embW[(size_t)w * 512 + k];
    }
    __syncthreads();

    int j0 = jc * 512 + tx * 8;
    ull acc[4][4];
#pragma unroll
    for (int a = 0; a < 4; ++a)
#pragma unroll
        for (int b = 0; b < 4; ++b) acc[a][b] = 0ull;

    const float* wp = g_Wt_ih + j0;
    int rb = ty * 4;
#pragma unroll 4
    for (int k = 0; k < 512; ++k) {
        float4 wa = *(const float4*)(wp);
        float4 wb = *(const float4*)(wp + 4);
        wp += 1536;
        ull b0 = pack2(wa.x, wa.y), b1 = pack2(wa.z, wa.w);
        ull b2 = pack2(wb.x, wb.y), b3 = pack2(wb.z, wb.w);
#pragma unroll
        for (int ri = 0; ri < 4; ++ri) {
            float h = ash[(rb + ri) * 514 + k];
            ull a2 = pack2(h, h);
            ffma2(acc[ri][0], a2, b0);
            ffma2(acc[ri][1], a2, b1);
            ffma2(acc[ri][2], a2, b2);
            ffma2(acc[ri][3], a2, b3);
        }
    }

    int t = rbase >> 5;
#pragma unroll
    for (int ri = 0; ri < 4; ++ri) {
        int r = rbase + rb + ri;
        int n = r & 31;
#pragma unroll
        for (int p = 0; p < 4; ++p) {
            float2 l = unpack2(acc[ri][p]);
            int j = j0 + 2 * p;
            g_Git[((size_t)t * 1536 + j) * NB + n]     = l.x + b_ih[j];
            g_Git[((size_t)t * 1536 + j + 1) * NB + n] = l.y + b_ih[j + 1];
        }
    }
}

// ---------------- persistent GRU v2: smem W + bulk h exchange + 2-level barrier ----------------
// 128 blocks x 512 threads; block owns j-rows [bx*4, bx*4+4).
// Per step: one 64KB cp.async.bulk stages h[t] to smem; dot loop is pure LDS/FFMA2.
__global__ __launch_bounds__(512) void gruPersist(const float* __restrict__ W_hh,
                                                  const float* __restrict__ b_hh) {
    extern __shared__ __align__(128) char gdsm[];
    float* Wsh = (float*)gdsm;                    // [gate3][jl4][k512]
    float* hsh = (float*)(gdsm + GW_BYTES);       // [k512][n32]
    __shared__ float part[3][4][4][32];
    __shared__ __align__(8) ull s_hmb[1];

    int tid = threadIdx.x;
    int n = tid & 31, ks = (tid >> 5) & 3, jl = tid >> 7;
    int bx = blockIdx.x;
    unsigned int mygen = g_gen;                   // replay-safe base (only tid0 uses)
    uint32 hmb = smem_u32(&s_hmb[0]);
    uint32 hshA = smem_u32(hsh);

    if (tid == 0) MBAR_INIT(hmb, 1);

    // preload W_hh slice into smem: Wsh[gate][jlw][k]
    for (int idx = tid; idx < 6144; idx += 512) {
        int gate = idx / 2048, rem = idx % 2048;
        int jlw = rem / 512, k = rem % 512;
        Wsh[idx] = W_hh[(size_t)(gate * 512 + bx * 4 + jlw) * 512 + k];
    }
    __syncthreads();

    // bulk h[0]
    if (tid == 0) {
        EXPECT_TX(hmb, GH_BYTES);
        BULK(hshA, (const char*)g_Hst, GH_BYTES, hmb);
    }

    int kb = ks * 128;
    const float* wr  = Wsh + (0 * 4 + jl) * 512 + kb;
    const float* wz  = Wsh + (1 * 4 + jl) * 512 + kb;
    const float* wnn = Wsh + (2 * 4 + jl) * 512 + kb;
    const float* hq  = hsh + kb * 32;

    // phase-2 mapping (tid < 128)
    int jl2 = tid >> 5, n2 = tid & 31;
    int j2 = bx * 4 + jl2;
    float bh0 = 0.f, bh1 = 0.f, bh2 = 0.f;
    const float* gitP = 0;
    __nv_bfloat16* aimgP = 0;
    float* hstP = 0;
    if (tid < 128) {
        bh0 = b_hh[j2]; bh1 = b_hh[j2 + 512]; bh2 = b_hh[j2 + 1024];
        gitP = g_Git + (size_t)j2 * 32 + n2;
        int kc = j2 >> 5, cc = j2 & 31;
        aimgP = g_Aimg + (size_t)kc * 5120 + cc;     // + r-dependent terms per step
        hstP = g_Hst + (size_t)HID * NB + j2 * 32 + n2;  // slot t+1 base
    }

    for (int t = 0; t < NSTEP; ++t) {
        // prefetch gate inputs (global; independent of the h bulk)
        float gr = 0.f, gz = 0.f, gn = 0.f;
        if (tid < 128) {
            const float* gp = gitP + (size_t)t * (1536 * 32);
            gr = gp[0];
            gz = gp[512 * 32];
            gn = gp[1024 * 32];
        }

        MBAR_WAIT(hmb, t & 1);      // h[t] staged in hsh

        ull ar2 = 0ull, az2 = 0ull, an2 = 0ull;
        ull br2 = 0ull, bz2 = 0ull, bn2 = 0ull;
#pragma unroll 8
        for (int k = 0; k < 128; k += 4) {
            ulonglong2 wr2 = *(const ulonglong2*)(wr + k);
            ulonglong2 wz2 = *(const ulonglong2*)(wz + k);
            ulonglong2 wn2 = *(const ulonglong2*)(wnn + k);
            float h0 = hq[(k + 0) * 32 + n];
            float h1 = hq[(k + 1) * 32 + n];
            float h2 = hq[(k + 2) * 32 + n];
            float h3 = hq[(k + 3) * 32 + n];
            ull hA = pack2(h0, h1), hB = pack2(h2, h3);
            ffma2(ar2, hA, wr2.x); ffma2(br2, hB, wr2.y);
            ffma2(az2, hA, wz2.x); ffma2(bz2, hB, wz2.y);
            ffma2(an2, hA, wn2.x); ffma2(bn2, hB, wn2.y);
        }
        {
            float2 u, v;
            u = unpack2(ar2); v = unpack2(br2); part[0][jl][ks][n] = u.x + u.y + v.x + v.y;
            u = unpack2(az2); v = unpack2(bz2); part[1][jl][ks][n] = u.x + u.y + v.x + v.y;
            u = unpack2(an2); v = unpack2(bn2); part[2][jl][ks][n] = u.x + u.y + v.x + v.y;
        }
        __syncthreads();

        if (tid < 128) {
            float hr = part[0][jl2][0][n2] + part[0][jl2][1][n2] + part[0][jl2][2][n2] + part[0][jl2][3][n2] + bh0;
            float hz = part[1][jl2][0][n2] + part[1][jl2][1][n2] + part[1][jl2][2][n2] + part[1][jl2][3][n2] + bh1;
            float hn = part[2][jl2][0][n2] + part[2][jl2][1][n2] + part[2][jl2][2][n2] + part[2][jl2][3][n2] + bh2;

            float rg_ = sigmoidf_(gr + hr);
            float zg  = sigmoidf_(gz + hz);
            float ng  = tanhf(gn + rg_ * hn);
            float hprev = hsh[j2 * 32 + n2];
            float hval = (1.0f - zg) * ng + zg * hprev;
            hstP[(size_t)t * (HID * NB)] = hval;

            // bf16 A image write: row r = t*32+n2 -> bt = r>>7, mr = r&127
            int r = t * 32 + n2;
            int btI = r >> 7, mr = r & 127;
            aimgP[(size_t)btI * (16 * 5120) + (size_t)mr * 40] = __float2bfloat16(hval);
        }
        __syncthreads();            // all hsh reads done; block's work complete

        if (tid == 0 && t < NSTEP - 1) {
            __threadfence();
            int grp = bx & 7;
            unsigned int old = atomicAdd(&g_cnt8[grp], 1);
            bool released = false;
            if (old == 15) {
                unsigned int o2 = atomicAdd(&g_top, 1);
                if (o2 == 7) {
#pragma unroll
                    for (int g = 0; g < 8; ++g) *((volatile unsigned int*)&g_cnt8[g]) = 0;
                    *((volatile unsigned int*)&g_top) = 0;
                    __threadfence();
                    atomicAdd(&g_gen, 1);
                    released = true;
                }
            }
            if (!released) {
                unsigned int cur;
                do {
                    asm volatile("ld.acquire.gpu.u32 %0, [%1];" : "=r"(cur) : "l"(&g_gen));
                } while (cur == mygen);
            }
            mygen++;
            // stage h[t+1] (others are blocked on the mbarrier until this lands)
            EXPECT_TX(hmb, GH_BYTES);
            BULK(hshA, (const char*)g_Hst + (size_t)(t + 1) * GH_BYTES, GH_BYTES, hmb);
        }
    }
}

// ---------------- emit GEMM (pure bf16 mma.sync) + fused logsumexp ----------------
__global__ __launch_bounds__(512, 1) void emitMMA() {
    extern __shared__ __align__(128) char dsm[];
    __shared__ float bsh[TN];
    __shared__ float redm[128][4], reds[128][4];
    __shared__ __align__(8) ull s_mbar[NRING];

    int tid = threadIdx.x, lane = tid & 31, w = tid >> 5;
    int mq = w & 3, nq = w >> 2;
    int rowBase = mq * 32, colBase = nq * 64;
    int bt = blockIdx.x, vt = blockIdx.y;
    int ro = bt * TM, vo = vt * TN;

    uint32 base = smem_u32(dsm);
    if (tid == 0) {
#pragma unroll
        for (int i = 0; i < NRING; ++i) MBAR_INIT(smem_u32(&s_mbar[i]), 1);
    }
    if (tid < TN) bsh[tid] = g_bpad[vo + tid];
    __syncthreads();
    uint32 mb[NRING];
#pragma unroll
    for (int i = 0; i < NRING; ++i) mb[i] = smem_u32(&s_mbar[i]);

    const char* srcA = (const char*)g_Aimg + (size_t)bt * 16 * ABLK;
    const char* srcB = (const char*)g_Wimg + (size_t)vt * 16 * BBLK;

    if (tid == 0) {
#pragma unroll
        for (int q = 0; q < NRING - 1; ++q) {
            uint32 qb = base + (uint32)q * STG1;
            EXPECT_TX(mb[q], STG1);
            BULK(qb,        srcA + (size_t)q * ABLK, ABLK, mb[q]);
            BULK(qb + ABLK, srcB + (size_t)q * BBLK, BBLK, mb[q]);
        }
    }

    int ar = (lane & 7) + ((lane >> 3) & 1) * 8, ac = ((lane >> 4) & 1) * 8;
    int br = (lane & 7) + ((lane >> 4) & 1) * 8, bc = ((lane >> 3) & 1) * 8;
    uint32 aOff0 = (uint32)((rowBase + ar) * 80 + ac * 2);
    uint32 aOff1 = (uint32)((rowBase + 16 + ar) * 80 + ac * 2);
    uint32 bOffs[4];
#pragma unroll
    for (int np = 0; np < 4; ++np) bOffs[np] = (uint32)((colBase + np * 16 + br) * 80 + bc * 2);

    float acc[2][8][4];
#pragma unroll
    for (int mt = 0; mt < 2; ++mt)
#pragma unroll
        for (int nt = 0; nt < 8; ++nt)
#pragma unroll
            for (int c = 0; c < 4; ++c) acc[mt][nt][c] = 0.0f;

#pragma unroll 1
    for (int s = 0; s < NSTG; ++s) {
        int slot = s % NRING;
        int phase = (s / NRING) & 1;
        if (tid == 0 && s + NRING - 1 < NSTG) {
            int q = s + NRING - 1;
            int qs = q % NRING;
            uint32 qb = base + (uint32)qs * STG1;
            EXPECT_TX(mb[qs], STG1);
            BULK(qb,        srcA + (size_t)q * ABLK, ABLK, mb[qs]);
            BULK(qb + ABLK, srcB + (size_t)q * BBLK, BBLK, mb[qs]);
        }
        MBAR_WAIT(mb[slot], phase);

        uint32 bufA = base + (uint32)slot * STG1;
        uint32 bufB = bufA + ABLK;
#pragma unroll
        for (int kbi = 0; kbi < 2; ++kbi) {
            uint32 ko = (uint32)(kbi * 32);
            uint32 af[2][4];
            LDSM4(af[0], bufA + aOff0 + ko);
            LDSM4(af[1], bufA + aOff1 + ko);
#pragma unroll
            for (int np = 0; np < 4; ++np) {
                uint32 bb[4];
                LDSM4(bb, bufB + bOffs[np] + ko);
#pragma unroll
                for (int mt = 0; mt < 2; ++mt) {
                    MMA_BF16(acc[mt][2 * np + 0], af[mt], bb[0], bb[1]);
                    MMA_BF16(acc[mt][2 * np + 1], af[mt], bb[2], bb[3]);
                }
            }
        }
        __syncthreads();
    }

    int g = lane >> 2, tg = lane & 3;
#pragma unroll
    for (int mt = 0; mt < 2; ++mt) {
#pragma unroll
        for (int h = 0; h < 2; ++h) {
            float x[16], m = -1e30f;
#pragma unroll
            for (int nt = 0; nt < 8; ++nt) {
#pragma unroll
                for (int c = 0; c < 2; ++c) {
                    float v = acc[mt][nt][2 * h + c] + bsh[colBase + nt * 8 + 2 * tg + c];
                    x[nt * 2 + c] = v;
                    m = fmaxf(m, v);
                }
            }
            float ssum = 0.0f;
#pragma unroll
            for (int i = 0; i < 16; ++i) ssum += fexp(x[i] - m);
#pragma unroll
            for (int o = 1; o <= 2; o <<= 1) {
                float m2 = __shfl_xor_sync(0xffffffffu, m, o);
                float s2 = __shfl_xor_sync(0xffffffffu, ssum, o);
                lse_combine(m, ssum, m2, s2);
            }
            if (tg == 0) {
                int rl = rowBase + mt * 16 + g + h * 8;
                redm[rl][nq] = m;
                reds[rl][nq] = ssum;
            }
        }
    }
    __syncthreads();
    if (tid < 128) {
        float M = -1e30f, S = 0.0f;
#pragma unroll
        for (int q = 0; q < 4; ++q) lse_combine(M, S, redm[tid][q], reds[tid][q]);
        int row = ro + tid;
        g_Pm[(size_t)vt * RPAD + row] = M;
        g_Ps[(size_t)vt * RPAD + row] = S;
    }
}

// ---------------- target logits ----------------
__global__ void tlogK(const int* __restrict__ words,
                      const float* __restrict__ emit_W,
                      const float* __restrict__ emit_b) {
    int gtid = blockIdx.x * blockDim.x + threadIdx.x;
    int warp = gtid >> 5;
    int lane = threadIdx.x & 31;
    if (warp >= NROWS) return;
    int t = warp >> 5, n = warp & 31;
    int tgt = words[n * TT + t + 1];
    const float* h = g_Hst + (size_t)(t + 1) * (HID * NB);
    const float* wv = emit_W + (size_t)tgt * 512;
    float s = 0.0f;
    for (int k = lane; k < 512; k += 32) s += h[k * NB + n] * wv[k];
#pragma unroll
    for (int o = 16; o; o >>= 1) s += __shfl_xor_sync(0xffffffffu, s, o);
    if (lane == 0) g_Tlog[warp] = s + emit_b[tgt];
}

// ---------------- finalize ----------------
__global__ void finK(float* __restrict__ out) {
    int n = blockIdx.x;
    int tid = threadIdx.x;
    __shared__ float sh[128];
    float v = 0.0f;
    if (tid < NSTEP) {
        int r = tid * NB + n;
        float M = -1e30f, S = 0.0f;
        for (int c = 0; c < NVT2; ++c)
            lse_combine(M, S, g_Pm[(size_t)c * RPAD + r], g_Ps[(size_t)c * RPAD + r]);
        v = g_Tlog[r] - (M + logf(S));
    }
    sh[tid] = v;
    __syncthreads();
    for (int o = 64; o; o >>= 1) { if (tid < o) sh[tid] += sh[tid + o]; __syncthreads(); }
    if (tid == 0) out[n] = sh[0] / (float)NSTEP;
}

// ---------------- h_final ----------------
__global__ void hfinK(float* __restrict__ out) {
    int idx = blockIdx.x * blockDim.x + threadIdx.x;
    int n = idx >> 9, k = idx & 511;
    out[32 + idx] = g_Hst[(size_t)127 * (HID * NB) + k * NB + n];
}

// ---------------- launch ----------------
extern "C" void kernel_launch(void* const* d_in, const int* in_sizes, int n_in,
                              void* d_out, int out_size) {
    const int*   words  = (const int*)d_in[0];
    const float* h0     = (const float*)d_in[1];
    const float* embW   = (const float*)d_in[2];
    const float* W_ih   = (const float*)d_in[3];
    const float* W_hh   = (const float*)d_in[4];
    const float* b_ih   = (const float*)d_in[5];
    const float* b_hh   = (const float*)d_in[6];
    const float* emit_W = (const float*)d_in[7];
    const float* emit_b = (const float*)d_in[8];
    float* out = (float*)d_out;

    static int configured = 0;
    if (!configured) {
        cudaFuncSetAttribute(emitMMA, cudaFuncAttributeMaxDynamicSharedMemorySize, DYNB);
        cudaFuncSetAttribute(gruPersist, cudaFuncAttributeMaxDynamicSharedMemorySize, GDYN);
        configured = 1;
    }

    // 1: B image build
    convWimg<<<dim3(NVT2 * 16, 32), 320>>>(emit_W);

    // 2: bpad + initH + W_ih transpose
    prepMisc<<<(PM_TOTAL + 255) / 256, 256>>>(emit_b, h0, W_ih);

    // 3: input-gate projections
    giK<<<dim3(3, 254), 256>>>(words, embW, b_ih);

    // 4: persistent GRU recurrence  (<-- profiled launch)
    gruPersist<<<NBLK, 512, GDYN>>>(W_hh, b_hh);

    // 5: emit GEMM + logsumexp
    emitMMA<<<dim3(32, NVT2), 512, DYNB>>>();

    tlogK<<<508, 256>>>(words, emit_W, emit_b);
    finK<<<32, 128>>>(out);
    hfinK<<<64, 256>>>(out);
}